// round 1
// baseline (speedup 1.0000x reference)
#include <cuda_runtime.h>
#include <math.h>

// ----------------------------------------------------------------------------
// Fused MLP3D kernel (fp32, SMEM-tiled).
// One block = 64 points, 256 threads.
// Activations live in SMEM transposed: buf[k][pt], row stride LDB=68 floats
// (16B-aligned rows, avoids systematic bank conflicts on transposed stores).
//
// Pipeline per block:
//   embed (63 feats, padded to 64 with a zero row)  -> bufB
//   GEMM0: x  = emb @ W0 + b0          (K=64/63)    -> bufA
//   GEMM1: h  = relu(x @ W1 + b1)      (K=256)      -> bufB
//   parts: for p: relu(x[:,p] @ W1[p,p] + b1[p]) . Wc[p] + bc[p]  (uses bufA)
//   GEMM2: h2 = relu(h @ W2 + b2)      (K=256)      -> bufA  (x dead)
//   occ:   h2 @ Wocc + bocc
//
// Output layout: d_out[0..n)            = occ   (B=1, [N,1] flattened)
//                d_out[n .. n + 4n)     = part_class ([N,4] row-major)
// ----------------------------------------------------------------------------

#define THREADS 256
#define TP      64          // points per block
#define LDB     68          // padded row stride (floats) for activation buffers
#define KC      32          // K-chunk for weight staging

// shared-memory float offsets
#define OFF_A   0
#define OFF_B   (256 * LDB)            // 17408
#define OFF_W   (2 * 256 * LDB)        // 34816  (Wt: KC*256 = 8192 floats)
#define OFF_RED (OFF_W + KC * 256)     // 43008  (sRed: 256 floats)
#define OFF_WC  (OFF_RED + 256)        // 43264  (sWc: 64 floats)
#define SMEM_FLOATS (OFF_WC + 64)      // 43328 floats = 173312 bytes

// out[i][j] = act( bias[j] + sum_k inT[k][i] * Wg[k][j] ), written transposed
// to outT[j][i]. Wg is row-major [Kact][256] in global. K is the (padded)
// loop bound; rows >= Kact are zero-filled (inT rows there must be zero).
__device__ __forceinline__ void gemm_tile(
    const float* __restrict__ Wg, const float* __restrict__ bias,
    const float* inT, float* outT, float* Wt,
    int K, int Kact, bool doRelu)
{
    const int t    = threadIdx.x;
    const int lane = t & 31;        // neuron group: j = lane + 32*r
    const int i0   = (t >> 5) * 8;  // point group (warp-uniform)

    float acc[8][8];
#pragma unroll
    for (int r = 0; r < 8; ++r)
#pragma unroll
        for (int i = 0; i < 8; ++i) acc[r][i] = 0.f;

    for (int k0 = 0; k0 < K; k0 += KC) {
        __syncthreads();
        // stage Wt[KC][256] (float4-coalesced, zero-fill beyond Kact)
#pragma unroll
        for (int r = 0; r < 8; ++r) {
            int idx4 = t + r * 256;           // 0..2047
            int row  = idx4 >> 6;             // 64 float4 per row
            int col  = (idx4 & 63) << 2;
            float4 v = make_float4(0.f, 0.f, 0.f, 0.f);
            int gk = k0 + row;
            if (gk < Kact) v = *(const float4*)(Wg + gk * 256 + col);
            *(float4*)(Wt + row * 256 + col) = v;
        }
        __syncthreads();

#pragma unroll 4
        for (int kk = 0; kk < KC; ++kk) {
            const float* xr = inT + (k0 + kk) * LDB + i0;   // warp-broadcast
            float4 xa = *(const float4*)xr;
            float4 xb = *(const float4*)(xr + 4);
            float xv[8] = {xa.x, xa.y, xa.z, xa.w, xb.x, xb.y, xb.z, xb.w};
            float wv[8];
#pragma unroll
            for (int r = 0; r < 8; ++r) wv[r] = Wt[kk * 256 + lane + 32 * r];
#pragma unroll
            for (int r = 0; r < 8; ++r)
#pragma unroll
                for (int i = 0; i < 8; ++i)
                    acc[r][i] = fmaf(wv[r], xv[i], acc[r][i]);
        }
    }

    // bias + activation + transposed store
#pragma unroll
    for (int r = 0; r < 8; ++r) {
        int j = lane + 32 * r;
        float b = bias[j];
#pragma unroll
        for (int i = 0; i < 8; ++i) {
            float v = acc[r][i] + b;
            if (doRelu) v = fmaxf(v, 0.f);
            outT[j * LDB + i0 + i] = v;
        }
    }
    __syncthreads();
}

extern "C" __global__ void __launch_bounds__(THREADS, 1)
mlp3d_kernel(const float* __restrict__ coords,
             const float* __restrict__ W0, const float* __restrict__ b0,
             const float* __restrict__ W1, const float* __restrict__ b1,
             const float* __restrict__ W2, const float* __restrict__ b2,
             const float* __restrict__ Wocc, const float* __restrict__ bocc,
             const float* __restrict__ Wc, const float* __restrict__ bc,
             float* __restrict__ out, int n)
{
    extern __shared__ float sm[];
    float* bufA = sm + OFF_A;
    float* bufB = sm + OFF_B;
    float* Wt   = sm + OFF_W;
    float* sRed = sm + OFF_RED;
    float* sWc  = sm + OFF_WC;

    const int t   = threadIdx.x;
    const int pt0 = blockIdx.x * TP;

    // ---- embedding -> bufB rows 0..62, row 63 zero-padded ----
    // emb layout: [x,y,z, sin(2^0 xyz), cos(2^0 xyz), sin(2^1 xyz), ...]
    if (t < TP) bufB[63 * LDB + t] = 0.f;
    if (t < TP * 3) {
        int pt = t / 3, d = t % 3;
        float c = 0.f;
        if (pt0 + pt < n) c = coords[(pt0 + pt) * 3 + d];
        bufB[d * LDB + pt] = c;
        float ang = c;
#pragma unroll
        for (int f = 0; f < 10; ++f) {
            float s, co;
            sincosf(ang, &s, &co);
            bufB[(3 + 6 * f + d) * LDB + pt]     = s;
            bufB[(3 + 6 * f + 3 + d) * LDB + pt] = co;
            ang += ang;   // exact *2
        }
    }
    __syncthreads();

    gemm_tile(W0, b0, bufB, bufA, Wt, 64, 63, false);    // x  -> bufA
    gemm_tile(W1, b1, bufA, bufB, Wt, 256, 256, true);   // h  -> bufB

    // ---- part branches (need x in bufA) ----
    {
        const int pt = t & 63;
        const int q  = t >> 6;         // warp-uniform j-quarter
        for (int p = 0; p < 4; ++p) {
            const int P = p * 64;
            // stage W1[P:P+64, P:P+64] into Wt (row stride 64 floats)
#pragma unroll
            for (int r = 0; r < 4; ++r) {
                int idx4 = t + r * 256;            // 0..1023
                int row  = idx4 >> 4;              // 16 float4 per row
                int col  = (idx4 & 15) << 2;
                *(float4*)(Wt + row * 64 + col) =
                    *(const float4*)(W1 + (P + row) * 256 + P + col);
            }
            if (t < 64) sWc[t] = Wc[p * 256 + P + t];
            __syncthreads();

            float acc[16];
#pragma unroll
            for (int jj = 0; jj < 16; ++jj) acc[jj] = b1[P + q * 16 + jj];
#pragma unroll
            for (int kc = 0; kc < 4; ++kc) {
                float xk[16];
#pragma unroll
                for (int k = 0; k < 16; ++k)
                    xk[k] = bufA[(P + kc * 16 + k) * LDB + pt];
#pragma unroll
                for (int jj = 0; jj < 16; ++jj)
#pragma unroll
                    for (int k = 0; k < 16; ++k)
                        acc[jj] = fmaf(xk[k],
                                       Wt[(kc * 16 + k) * 64 + q * 16 + jj],
                                       acc[jj]);
            }
            float s = 0.f;
#pragma unroll
            for (int jj = 0; jj < 16; ++jj)
                s = fmaf(fmaxf(acc[jj], 0.f), sWc[q * 16 + jj], s);
            sRed[q * 64 + pt] = s;
            __syncthreads();
            if (t < 64 && pt0 + t < n) {
                float cls = bc[p] + sRed[t] + sRed[64 + t]
                                  + sRed[128 + t] + sRed[192 + t];
                out[n + (pt0 + t) * 4 + p] = cls;
            }
            __syncthreads();
        }
    }

    gemm_tile(W2, b2, bufB, bufA, Wt, 256, 256, true);   // h2 -> bufA

    // ---- occ head ----
    Wt[t] = Wocc[t];
    __syncthreads();
    {
        const int pt = t & 63;
        const int q  = t >> 6;
        float s = 0.f;
#pragma unroll
        for (int j = 0; j < 64; ++j)
            s = fmaf(bufA[(q * 64 + j) * LDB + pt], Wt[q * 64 + j], s);
        sRed[q * 64 + pt] = s;
        __syncthreads();
        if (t < 64 && pt0 + t < n)
            out[pt0 + t] = bocc[0] + sRed[t] + sRed[64 + t]
                                   + sRed[128 + t] + sRed[192 + t];
    }
}

extern "C" void kernel_launch(void* const* d_in, const int* in_sizes, int n_in,
                              void* d_out, int out_size)
{
    const float* coords = (const float*)d_in[0];
    const float* W0   = (const float*)d_in[1];
    const float* b0   = (const float*)d_in[2];
    const float* W1   = (const float*)d_in[3];
    const float* b1   = (const float*)d_in[4];
    const float* W2   = (const float*)d_in[5];
    const float* b2   = (const float*)d_in[6];
    const float* Wocc = (const float*)d_in[7];
    const float* bocc = (const float*)d_in[8];
    const float* Wc   = (const float*)d_in[9];
    const float* bc   = (const float*)d_in[10];
    float* out = (float*)d_out;

    int n = in_sizes[0] / 3;
    int blocks = (n + TP - 1) / TP;
    size_t smem = SMEM_FLOATS * sizeof(float);
    cudaFuncSetAttribute(mlp3d_kernel,
                         cudaFuncAttributeMaxDynamicSharedMemorySize,
                         (int)smem);
    mlp3d_kernel<<<blocks, THREADS, smem>>>(coords, W0, b0, W1, b1, W2, b2,
                                            Wocc, bocc, Wc, bc, out, n);
}